// round 14
// baseline (speedup 1.0000x reference)
#include <cstdint>
#include <cuda_runtime.h>
#include <cuda_bf16.h>
#include <cuda_fp16.h>

// ---------------------------------------------------------------------------
// GnnEncoder: 3-layer GraphSAGE (mean aggr) + ReLU + LayerNorm.
// R13 = R12 with ONE change: k_agg gathers 2 edges per warp iteration
// (half-warp per edge, uint4 = 16B x 16 lanes = full fp16 row), halving
// warp-level request count per edge + 2x unroll (4 edges in flight).
// Tests the "agg is request-bound, not byte-bound" hypothesis (R12 neutral
// on byte halving). GEMM path unchanged: fp32 mem, bf16x3 MMA.
// ---------------------------------------------------------------------------

static constexpr int NN = 50000;
static constexpr int EE = 800000;
static constexpr int C  = 128;

// scratch (static __device__ allocations: allowed)
__device__ float g_mean[NN * C];
__device__ float g_h1[NN * C];
__device__ float g_h2[NN * C];
__device__ __half g_x16[NN * C];
__device__ __half g_h1x16[NN * C];
__device__ __half g_h2x16[NN * C];
__device__ __nv_bfloat16 g_w1h[128 * 256];
__device__ __nv_bfloat16 g_w1l[128 * 256];
__device__ __nv_bfloat16 g_w2h[128 * 256];
__device__ __nv_bfloat16 g_w2l[128 * 256];
__device__ __nv_bfloat16 g_w3h[64 * 256];
__device__ __nv_bfloat16 g_w3l[64 * 256];
__device__ int   g_src[EE];
__device__ int   g_dst[EE];
__device__ int   g_csr[EE];
__device__ int   g_off[NN + 1];
__device__ int   g_cnt[NN];
__device__ int   g_cur[NN];
__device__ int   g_bsum[64];
__device__ int   g_bsumx[64];
__device__ float g_invc[NN];
__device__ int   g_is64;

// --------------------------- index prep ------------------------------------

__global__ void k_detect(const unsigned* __restrict__ buf) {
    int nz = 0;
    for (int i = threadIdx.x; i < 512; i += blockDim.x)
        if (buf[2 * i + 1] != 0u) nz = 1;
    nz = __syncthreads_or(nz);
    if (threadIdx.x == 0) g_is64 = (nz == 0) ? 1 : 0;
}

__global__ void k_zero(int n) {
    int i = blockIdx.x * blockDim.x + threadIdx.x;
    if (i < n) { g_cnt[i] = 0; g_cur[i] = 0; }
}

// convert edge indices to int32 AND histogram dst (fused)
__global__ void k_convert(const void* __restrict__ buf, int E) {
    int e = blockIdx.x * blockDim.x + threadIdx.x;
    if (e >= E) return;
    int s, d;
    if (g_is64) {
        const long long* p = (const long long*)buf;
        s = (int)p[e]; d = (int)p[E + e];
    } else {
        const int* p = (const int*)buf;
        s = p[e]; d = p[E + e];
    }
    g_src[e] = s; g_dst[e] = d;
    atomicAdd(&g_cnt[d], 1);
}

// ---- hierarchical scan: 49 blocks x 1024 -> 64-wide block-sum scan -> add ----
__global__ __launch_bounds__(1024) void k_scan1(int n) {
    __shared__ int sh[1024];
    const int tid = threadIdx.x;
    int i = blockIdx.x * 1024 + tid;
    int v = (i < n) ? g_cnt[i] : 0;
    sh[tid] = v;
    __syncthreads();
    for (int off = 1; off < 1024; off <<= 1) {
        int t = (tid >= off) ? sh[tid - off] : 0;
        __syncthreads();
        sh[tid] += t;
        __syncthreads();
    }
    if (i < n) g_off[i] = sh[tid] - v;        // exclusive within block
    if (tid == 1023) g_bsum[blockIdx.x] = sh[1023];
}

__global__ void k_scan2(int nb) {
    __shared__ int sh[64];
    const int tid = threadIdx.x;
    int v = (tid < nb) ? g_bsum[tid] : 0;
    sh[tid] = v;
    __syncthreads();
    for (int off = 1; off < 64; off <<= 1) {
        int t = (tid >= off) ? sh[tid - off] : 0;
        __syncthreads();
        sh[tid] += t;
        __syncthreads();
    }
    if (tid < nb) g_bsumx[tid] = sh[tid] - v; // exclusive
}

// add block offsets; also compute invc (fused). g_off[n] = E (known total).
__global__ void k_scan3(int n, int E) {
    int i = blockIdx.x * blockDim.x + threadIdx.x;
    if (i < n) {
        g_off[i] += g_bsumx[i >> 10];
        int cnt = g_cnt[i];
        g_invc[i] = 1.0f / (float)(cnt > 0 ? cnt : 1);
    }
    if (i == 0) g_off[n] = E;
}

__global__ void k_scatter(int E) {
    int e = blockIdx.x * blockDim.x + threadIdx.x;
    if (e >= E) return;
    int d = g_dst[e];
    int p = atomicAdd(&g_cur[d], 1);
    g_csr[g_off[d] + p] = g_src[e];
}

// --------------------------- conversions -----------------------------------

// x (fp32) -> fp16 shadow plane for aggregation
__global__ void k_cvt_x(const float* __restrict__ x, int total) {
    int i = (blockIdx.x * blockDim.x + threadIdx.x) * 4;
    if (i >= total) return;
    float4 v = *(const float4*)(x + i);
    __half2 p0 = __floats2half2_rn(v.x, v.y);
    __half2 p1 = __floats2half2_rn(v.z, v.w);
    uint2 o;
    o.x = *(unsigned*)&p0; o.y = *(unsigned*)&p1;
    *(uint2*)(g_x16 + i) = o;
}

// weights: dst[n][k] (k<128: Wl, else Wr) -> bf16 hi + residual lo
__global__ void k_cvt_w(const float* __restrict__ Wl, const float* __restrict__ Wr,
                        __nv_bfloat16* __restrict__ dh, __nv_bfloat16* __restrict__ dl,
                        int N) {
    int i = blockIdx.x * blockDim.x + threadIdx.x;
    if (i >= N * 256) return;
    int nrow = i >> 8, k = i & 255;
    float v = (k < 128) ? Wl[nrow * 128 + k] : Wr[nrow * 128 + (k - 128)];
    __nv_bfloat16 h = __float2bfloat16(v);
    dh[i] = h;
    dl[i] = __float2bfloat16(v - __bfloat162float(h));
}

// --------------------------- aggregation -----------------------------------
// warp-per-node; HALF-warp per edge: 16 lanes x uint4 (16B) = full fp16 row.
// 2 edges per warp iteration + 2x unroll = 4 edge-rows in flight.
__global__ __launch_bounds__(256) void k_agg(int insel, int n) {
    const __half* xin = (insel == 0) ? g_x16 : (insel == 1) ? g_h1x16 : g_h2x16;
    int warp = (blockIdx.x * blockDim.x + threadIdx.x) >> 5;
    int lane = threadIdx.x & 31;
    if (warp >= n) return;
    const int s0 = g_off[warp], s1 = g_off[warp + 1];
    const int half = lane >> 4;       // 0 or 1
    const int l16 = lane & 15;
    const uint4* x4 = (const uint4*)xin;   // 16 uint4 per 128-half row

    float a[8];
#pragma unroll
    for (int j = 0; j < 8; j++) a[j] = 0.f;

    auto accum = [&](int edge) {
        int node = g_csr[edge];
        uint4 u = x4[node * 16 + l16];
        float2 f0 = __half22float2(*(__half2*)&u.x);
        float2 f1 = __half22float2(*(__half2*)&u.y);
        float2 f2 = __half22float2(*(__half2*)&u.z);
        float2 f3 = __half22float2(*(__half2*)&u.w);
        a[0] += f0.x; a[1] += f0.y; a[2] += f1.x; a[3] += f1.y;
        a[4] += f2.x; a[5] += f2.y; a[6] += f3.x; a[7] += f3.y;
    };

    int i = s0 + half;
    for (; i + 2 < s1; i += 4) {        // 2 edges per half-warp in flight
        accum(i);
        accum(i + 2);
    }
    if (i < s1) accum(i);

    // merge the two half-warp partial sums (cols identical across halves)
#pragma unroll
    for (int j = 0; j < 8; j++)
        a[j] += __shfl_xor_sync(0xffffffffu, a[j], 16);

    float ic = g_invc[warp];
    float4 o = make_float4(a[half * 4 + 0] * ic, a[half * 4 + 1] * ic,
                           a[half * 4 + 2] * ic, a[half * 4 + 3] * ic);
    // col group = l16*8 + half*4  ->  float4 index l16*2 + half
    ((float4*)g_mean)[warp * 32 + l16 * 2 + half] = o;
}

// --------------------------- tensor-core GEMM (bf16x3) ----------------------

__device__ __forceinline__ void mma16816(float* c, const unsigned* a, const unsigned* b) {
    asm volatile(
        "mma.sync.aligned.m16n8k16.row.col.f32.bf16.bf16.f32 "
        "{%0,%1,%2,%3}, {%4,%5,%6,%7}, {%8,%9}, {%0,%1,%2,%3};\n"
        : "+f"(c[0]), "+f"(c[1]), "+f"(c[2]), "+f"(c[3])
        : "r"(a[0]), "r"(a[1]), "r"(a[2]), "r"(a[3]), "r"(b[0]), "r"(b[1]));
}
__device__ __forceinline__ void ldsm4(unsigned* r, uint32_t addr) {
    asm volatile("ldmatrix.sync.aligned.m8n8.x4.shared.b16 {%0,%1,%2,%3}, [%4];\n"
        : "=r"(r[0]), "=r"(r[1]), "=r"(r[2]), "=r"(r[3]) : "r"(addr));
}

// out[m][j] = sum_k mean[m][k]*W[j][k] + sum_k Ax[m][k]*W[j][128+k] + bias[j]
// FUSE: + ReLU + LayerNorm; writes fp32 out AND fp16 shadow (for next agg).
// BM=128, BK=32, 256 threads (8 warps), warp tile m16 x nBN (whole rows).
// Pipeline: LDG tile t+2 -> regs, STS tile t+1 -> alt smem stage, compute t.
template <int BN, bool FUSE>
__global__ __launch_bounds__(256) void k_mma(
    const float* __restrict__ Ax,
    const __nv_bfloat16* __restrict__ Wh,      // [BN][256] concat [Wl|Wr] hi
    const __nv_bfloat16* __restrict__ Wl_,     // lo
    const float* __restrict__ bias,
    const float* __restrict__ gamma, const float* __restrict__ beta,
    float* __restrict__ out, __half* __restrict__ out16, int n)
{
    constexpr int BM = 128, BK = 32;
    constexpr int LDA = BK + 8;            // 40 bf16 row stride (80B, 16B-mult)
    constexpr int NT = BN / 8;             // n-tiles per warp row stripe
    constexpr int NB = (BN * 4) / 256;     // B chunks per thread (2 or 1)
    constexpr int AH = 0;
    constexpr int AL = BM * LDA;
    constexpr int BH = 2 * BM * LDA;
    constexpr int BL = 2 * BM * LDA + BN * LDA;
    constexpr int STAGE = 2 * BM * LDA + 2 * BN * LDA;   // elements
    constexpr int STAGE_B = STAGE * 2;                    // bytes

    extern __shared__ __align__(16) __nv_bfloat16 smem[];

    const int tid = threadIdx.x;
    const int lane = tid & 31, warp = tid >> 5;
    const int rowBase = blockIdx.x * BM;
    const uint32_t sBase = (uint32_t)__cvta_generic_to_shared(smem);

    float c[NT][4];
#pragma unroll
    for (int j = 0; j < NT; j++)
#pragma unroll
        for (int q = 0; q < 4; q++) c[j][q] = 0.f;

    float va[2][8];
    uint4 vbh[2], vbl[2];

    auto ldg_tile = [&](int t) {
        const float* A = (t < 4) ? g_mean : Ax;
        const int k0 = (t & 3) * BK;
#pragma unroll
        for (int i = 0; i < 2; i++) {
            int q = tid + i * 256;
            int row = q >> 2, c8 = q & 3;
            int gr = rowBase + row;
            if (gr < n) {
                float4 v0 = *(const float4*)(A + gr * 128 + k0 + c8 * 8);
                float4 v1 = *(const float4*)(A + gr * 128 + k0 + c8 * 8 + 4);
                va[i][0] = v0.x; va[i][1] = v0.y; va[i][2] = v0.z; va[i][3] = v0.w;
                va[i][4] = v1.x; va[i][5] = v1.y; va[i][6] = v1.z; va[i][7] = v1.w;
            } else {
#pragma unroll
                for (int j = 0; j < 8; j++) va[i][j] = 0.f;
            }
        }
#pragma unroll
        for (int i = 0; i < NB; i++) {
            int q = tid + i * 256;
            int row = q >> 2, c8 = q & 3;
            vbh[i] = *(const uint4*)(Wh  + row * 256 + t * BK + c8 * 8);
            vbl[i] = *(const uint4*)(Wl_ + row * 256 + t * BK + c8 * 8);
        }
    };
    auto sts_tile = [&](int s) {
        __nv_bfloat16* st = smem + s * STAGE;
#pragma unroll
        for (int i = 0; i < 2; i++) {
            int q = tid + i * 256;
            int row = q >> 2, c8 = q & 3;
            __nv_bfloat16 h[8], l[8];
#pragma unroll
            for (int j = 0; j < 8; j++) {
                h[j] = __float2bfloat16(va[i][j]);
                l[j] = __float2bfloat16(va[i][j] - __bfloat162float(h[j]));
            }
            *(uint4*)(st + AH + row * LDA + c8 * 8) = *(uint4*)h;
            *(uint4*)(st + AL + row * LDA + c8 * 8) = *(uint4*)l;
        }
#pragma unroll
        for (int i = 0; i < NB; i++) {
            int q = tid + i * 256;
            int row = q >> 2, c8 = q & 3;
            *(uint4*)(st + BH + row * LDA + c8 * 8) = vbh[i];
            *(uint4*)(st + BL + row * LDA + c8 * 8) = vbl[i];
        }
    };

    const uint32_t aOff =
        (uint32_t)(((warp * 16 + (lane & 15)) * LDA + ((lane >> 4) << 3)) * 2);
    const int bRow = (lane & 7) + ((lane >> 4) << 3);   // n within 16-tile
    const int bKof = ((lane >> 3) & 1) << 3;            // k offset 0/8

    ldg_tile(0);
    sts_tile(0);
    ldg_tile(1);

    for (int t = 0; t < 8; t++) {
        __syncthreads();
        if (t + 1 < 8) sts_tile((t + 1) & 1);
        if (t + 2 < 8) ldg_tile(t + 2);

        const uint32_t st = sBase + (t & 1) * STAGE_B;
#pragma unroll
        for (int kk = 0; kk < BK; kk += 16) {
            unsigned ah[4], al[4];
            ldsm4(ah, st + AH * 2 + aOff + (uint32_t)(kk * 2));
            ldsm4(al, st + AL * 2 + aOff + (uint32_t)(kk * 2));
#pragma unroll
            for (int jp = 0; jp < NT / 2; jp++) {
                unsigned bh[4], bl[4];
                uint32_t bo = (uint32_t)(((jp * 16 + bRow) * LDA + kk + bKof) * 2);
                ldsm4(bh, st + BH * 2 + bo);
                ldsm4(bl, st + BL * 2 + bo);
                mma16816(c[2 * jp], ah, bh);
                mma16816(c[2 * jp], ah, bl);
                mma16816(c[2 * jp], al, bh);
                mma16816(c[2 * jp + 1], ah, bh + 2);
                mma16816(c[2 * jp + 1], ah, bl + 2);
                mma16816(c[2 * jp + 1], al, bh + 2);
            }
        }
    }

    // ---- epilogue ----
    const int r0 = rowBase + warp * 16 + (lane >> 2);
    const int r1 = r0 + 8;
    const int cb = (lane & 3) * 2;

    if constexpr (FUSE) {
        float s0 = 0.f, ss0 = 0.f, s1 = 0.f, ss1 = 0.f;
#pragma unroll
        for (int j = 0; j < NT; j++) {
            float b0 = bias[j * 8 + cb], b1 = bias[j * 8 + cb + 1];
            c[j][0] = fmaxf(c[j][0] + b0, 0.f);
            c[j][1] = fmaxf(c[j][1] + b1, 0.f);
            c[j][2] = fmaxf(c[j][2] + b0, 0.f);
            c[j][3] = fmaxf(c[j][3] + b1, 0.f);
            s0 += c[j][0] + c[j][1]; ss0 += c[j][0] * c[j][0] + c[j][1] * c[j][1];
            s1 += c[j][2] + c[j][3]; ss1 += c[j][2] * c[j][2] + c[j][3] * c[j][3];
        }
#pragma unroll
        for (int o = 1; o <= 2; o <<= 1) {
            s0 += __shfl_xor_sync(0xffffffffu, s0, o);
            ss0 += __shfl_xor_sync(0xffffffffu, ss0, o);
            s1 += __shfl_xor_sync(0xffffffffu, s1, o);
            ss1 += __shfl_xor_sync(0xffffffffu, ss1, o);
        }
        const float inv = 1.0f / 128.0f;
        float mu0 = s0 * inv, var0 = ss0 * inv - mu0 * mu0;
        float mu1 = s1 * inv, var1 = ss1 * inv - mu1 * mu1;
        float rs0 = rsqrtf(var0 + 1e-5f);
        float rs1 = rsqrtf(var1 + 1e-5f);
#pragma unroll
        for (int j = 0; j < NT; j++) {
            float g0 = gamma[j * 8 + cb], g1v = gamma[j * 8 + cb + 1];
            float e0 = beta[j * 8 + cb],  e1 = beta[j * 8 + cb + 1];
            if (r0 < n) {
                float v0 = (c[j][0] - mu0) * rs0 * g0 + e0;
                float v1 = (c[j][1] - mu0) * rs0 * g1v + e1;
                *(float2*)(out + r0 * 128 + j * 8 + cb) = make_float2(v0, v1);
                *(__half2*)(out16 + r0 * 128 + j * 8 + cb) = __floats2half2_rn(v0, v1);
            }
            if (r1 < n) {
                float v0 = (c[j][2] - mu1) * rs1 * g0 + e0;
                float v1 = (c[j][3] - mu1) * rs1 * g1v + e1;
                *(float2*)(out + r1 * 128 + j * 8 + cb) = make_float2(v0, v1);
                *(__half2*)(out16 + r1 * 128 + j * 8 + cb) = __floats2half2_rn(v0, v1);
            }
        }
    } else {
#pragma unroll
        for (int j = 0; j < NT; j++) {
            float b0 = bias[j * 8 + cb], b1 = bias[j * 8 + cb + 1];
            if (r0 < n)
                *(float2*)(out + r0 * BN + j * 8 + cb) =
                    make_float2(c[j][0] + b0, c[j][1] + b1);
            if (r1 < n)
                *(float2*)(out + r1 * BN + j * 8 + cb) =
                    make_float2(c[j][2] + b0, c[j][3] + b1);
        }
    }
}

// --------------------------- launch ----------------------------------------

extern "C" void kernel_launch(void* const* d_in, const int* in_sizes, int n_in,
                              void* d_out, int out_size)
{
    const float* x   = (const float*)d_in[0];
    const void*  ei  = d_in[1];
    const float* Wl1 = (const float*)d_in[2];
    const float* bl1 = (const float*)d_in[3];
    const float* Wr1 = (const float*)d_in[4];
    const float* Wl2 = (const float*)d_in[5];
    const float* bl2 = (const float*)d_in[6];
    const float* Wr2 = (const float*)d_in[7];
    const float* Wl3 = (const float*)d_in[8];
    const float* bl3 = (const float*)d_in[9];
    const float* Wr3 = (const float*)d_in[10];
    const float* g1  = (const float*)d_in[11];
    const float* be1 = (const float*)d_in[12];
    const float* g2  = (const float*)d_in[13];
    const float* be2 = (const float*)d_in[14];

    const int n = in_sizes[0] / C;       // 50000
    const int E = in_sizes[1] / 2;       // 800000

    const int TB = 256;
    const int nb = (n + 1023) / 1024;    // 49 scan blocks

    // dynamic smem (2 stages): BN=128 -> 81920B, BN=64 -> 61440B
    constexpr int LDA = 40;
    const int smem128 = 2 * (2 * 128 * LDA + 2 * 128 * LDA) * 2;
    const int smem64  = 2 * (2 * 128 * LDA + 2 * 64  * LDA) * 2;
    static bool attr_done = false;
    if (!attr_done) {
        cudaFuncSetAttribute(k_mma<128, true>,
            cudaFuncAttributeMaxDynamicSharedMemorySize, smem128);
        cudaFuncSetAttribute(k_mma<64, false>,
            cudaFuncAttributeMaxDynamicSharedMemorySize, smem64);
        attr_done = true;
    }

    // ---- CSR build (parallel scan) + conversions ----
    k_detect<<<1, TB>>>((const unsigned*)ei);
    k_zero<<<(n + TB - 1) / TB, TB>>>(n);
    k_convert<<<(E + TB - 1) / TB, TB>>>(ei, E);      // + hist
    k_scan1<<<nb, 1024>>>(n);
    k_scan2<<<1, 64>>>(nb);
    k_scan3<<<(n + TB - 1) / TB, TB>>>(n, E);          // + invc
    k_scatter<<<(E + TB - 1) / TB, TB>>>(E);

    k_cvt_x<<<(n * C / 4 + TB - 1) / TB, TB>>>(x, n * C);
    __nv_bfloat16 *w1h, *w1l, *w2h, *w2l, *w3h, *w3l;
    cudaGetSymbolAddress((void**)&w1h, g_w1h);
    cudaGetSymbolAddress((void**)&w1l, g_w1l);
    cudaGetSymbolAddress((void**)&w2h, g_w2h);
    cudaGetSymbolAddress((void**)&w2l, g_w2l);
    cudaGetSymbolAddress((void**)&w3h, g_w3h);
    cudaGetSymbolAddress((void**)&w3l, g_w3l);
    k_cvt_w<<<(128 * 256 + TB - 1) / TB, TB>>>(Wl1, Wr1, w1h, w1l, 128);
    k_cvt_w<<<(128 * 256 + TB - 1) / TB, TB>>>(Wl2, Wr2, w2h, w2l, 128);
    k_cvt_w<<<(64 * 256 + TB - 1) / TB, TB>>>(Wl3, Wr3, w3h, w3l, 64);

    float *h1p, *h2p;
    cudaGetSymbolAddress((void**)&h1p, g_h1);
    cudaGetSymbolAddress((void**)&h2p, g_h2);
    __half *h1x, *h2x;
    cudaGetSymbolAddress((void**)&h1x, g_h1x16);
    cudaGetSymbolAddress((void**)&h2x, g_h2x16);

    const int aggGrid  = (n + 7) / 8;       // 8 warps/block, warp per node
    const int gemmGrid = (n + 127) / 128;

    // ---- layer 1 ----
    k_agg<<<aggGrid, TB>>>(0, n);
    k_mma<128, true><<<gemmGrid, TB, smem128>>>(x, w1h, w1l, bl1, g1, be1,
                                                h1p, h1x, n);
    // ---- layer 2 ----
    k_agg<<<aggGrid, TB>>>(1, n);
    k_mma<128, true><<<gemmGrid, TB, smem128>>>(h1p, w2h, w2l, bl2, g2, be2,
                                                h2p, h2x, n);
    // ---- layer 3 (64 outputs, no ReLU/LN) ----
    k_agg<<<aggGrid, TB>>>(2, n);
    k_mma<64, false><<<gemmGrid, TB, smem64>>>(h2p, w3h, w3l, bl3,
                                               nullptr, nullptr,
                                               (float*)d_out, nullptr, n);
}

// round 16
// speedup vs baseline: 1.0109x; 1.0109x over previous
#include <cstdint>
#include <cuda_runtime.h>
#include <cuda_bf16.h>

// ---------------------------------------------------------------------------
// GnnEncoder: 3-layer GraphSAGE (mean aggr) + ReLU + LayerNorm.
// R15: tcgen05 is NOT compilable in this harness (PTX stage targets
// compute_103 without 'a' -> ptxas rejects). Revert to mma.sync bf16x3.
// ONE change vs the R10/R11 family: k_mma uses the simple 2-sync mainloop
// (40KB static smem, low regs) with __launch_bounds__(256, 2) -> 2 CTAs/SM,
// so cross-CTA overlap hides the sync-exposed load latency that the R11
// intra-CTA pipeline only partially covered.
// ---------------------------------------------------------------------------

static constexpr int NN = 50000;
static constexpr int EE = 800000;
static constexpr int C  = 128;

// scratch (static __device__ allocations: allowed)
__device__ float g_mean[NN * C];
__device__ float g_h1[NN * C];
__device__ float g_h2[NN * C];
__device__ __nv_bfloat16 g_w1h[128 * 256];
__device__ __nv_bfloat16 g_w1l[128 * 256];
__device__ __nv_bfloat16 g_w2h[128 * 256];
__device__ __nv_bfloat16 g_w2l[128 * 256];
__device__ __nv_bfloat16 g_w3h[64 * 256];
__device__ __nv_bfloat16 g_w3l[64 * 256];
__device__ int   g_src[EE];
__device__ int   g_dst[EE];
__device__ int   g_csr[EE];
__device__ int   g_off[NN + 1];
__device__ int   g_cnt[NN];
__device__ int   g_cur[NN];
__device__ int   g_bsum[64];
__device__ int   g_bsumx[64];
__device__ float g_invc[NN];
__device__ int   g_is64;

// --------------------------- index prep ------------------------------------

__global__ void k_detect(const unsigned* __restrict__ buf) {
    int nz = 0;
    for (int i = threadIdx.x; i < 512; i += blockDim.x)
        if (buf[2 * i + 1] != 0u) nz = 1;
    nz = __syncthreads_or(nz);
    if (threadIdx.x == 0) g_is64 = (nz == 0) ? 1 : 0;
}

__global__ void k_zero(int n) {
    int i = blockIdx.x * blockDim.x + threadIdx.x;
    if (i < n) { g_cnt[i] = 0; g_cur[i] = 0; }
}

// convert edge indices to int32 AND histogram dst (fused)
__global__ void k_convert(const void* __restrict__ buf, int E) {
    int e = blockIdx.x * blockDim.x + threadIdx.x;
    if (e >= E) return;
    int s, d;
    if (g_is64) {
        const long long* p = (const long long*)buf;
        s = (int)p[e]; d = (int)p[E + e];
    } else {
        const int* p = (const int*)buf;
        s = p[e]; d = p[E + e];
    }
    g_src[e] = s; g_dst[e] = d;
    atomicAdd(&g_cnt[d], 1);
}

// ---- hierarchical scan ----
__global__ __launch_bounds__(1024) void k_scan1(int n) {
    __shared__ int sh[1024];
    const int tid = threadIdx.x;
    int i = blockIdx.x * 1024 + tid;
    int v = (i < n) ? g_cnt[i] : 0;
    sh[tid] = v;
    __syncthreads();
    for (int off = 1; off < 1024; off <<= 1) {
        int t = (tid >= off) ? sh[tid - off] : 0;
        __syncthreads();
        sh[tid] += t;
        __syncthreads();
    }
    if (i < n) g_off[i] = sh[tid] - v;        // exclusive within block
    if (tid == 1023) g_bsum[blockIdx.x] = sh[1023];
}

__global__ void k_scan2(int nb) {
    __shared__ int sh[64];
    const int tid = threadIdx.x;
    int v = (tid < nb) ? g_bsum[tid] : 0;
    sh[tid] = v;
    __syncthreads();
    for (int off = 1; off < 64; off <<= 1) {
        int t = (tid >= off) ? sh[tid - off] : 0;
        __syncthreads();
        sh[tid] += t;
        __syncthreads();
    }
    if (tid < nb) g_bsumx[tid] = sh[tid] - v; // exclusive
}

__global__ void k_scan3(int n, int E) {
    int i = blockIdx.x * blockDim.x + threadIdx.x;
    if (i < n) {
        g_off[i] += g_bsumx[i >> 10];
        int cnt = g_cnt[i];
        g_invc[i] = 1.0f / (float)(cnt > 0 ? cnt : 1);
    }
    if (i == 0) g_off[n] = E;
}

__global__ void k_scatter(int E) {
    int e = blockIdx.x * blockDim.x + threadIdx.x;
    if (e >= E) return;
    int d = g_dst[e];
    int p = atomicAdd(&g_cur[d], 1);
    g_csr[g_off[d] + p] = g_src[e];
}

// --------------------------- weight split ----------------------------------
__global__ void k_cvt_w(const float* __restrict__ Wl, const float* __restrict__ Wr,
                        __nv_bfloat16* __restrict__ dh, __nv_bfloat16* __restrict__ dl,
                        int N) {
    int i = blockIdx.x * blockDim.x + threadIdx.x;
    if (i >= N * 256) return;
    int nrow = i >> 8, k = i & 255;
    float v = (k < 128) ? Wl[nrow * 128 + k] : Wr[nrow * 128 + (k - 128)];
    __nv_bfloat16 h = __float2bfloat16(v);
    dh[i] = h;
    dl[i] = __float2bfloat16(v - __bfloat162float(h));
}

// --------------------------- aggregation (fp32) -----------------------------
__global__ __launch_bounds__(256) void k_agg(const float* __restrict__ xext,
                                             int insel, int n) {
    const float* xin = (insel == 0) ? xext : (insel == 1) ? g_h1 : g_h2;
    int warp = (blockIdx.x * blockDim.x + threadIdx.x) >> 5;
    int lane = threadIdx.x & 31;
    if (warp >= n) return;
    int s0 = g_off[warp], s1 = g_off[warp + 1];
    const float4* xin4 = (const float4*)xin;
    float4 acc = make_float4(0.f, 0.f, 0.f, 0.f);
    int i = s0;
    for (; i + 1 < s1; i += 2) {
        int a = g_csr[i], b = g_csr[i + 1];
        float4 va = xin4[a * 32 + lane];
        float4 vb = xin4[b * 32 + lane];
        acc.x += va.x + vb.x; acc.y += va.y + vb.y;
        acc.z += va.z + vb.z; acc.w += va.w + vb.w;
    }
    if (i < s1) {
        int a = g_csr[i];
        float4 va = xin4[a * 32 + lane];
        acc.x += va.x; acc.y += va.y; acc.z += va.z; acc.w += va.w;
    }
    float ic = g_invc[warp];
    acc.x *= ic; acc.y *= ic; acc.z *= ic; acc.w *= ic;
    ((float4*)g_mean)[warp * 32 + lane] = acc;
}

// --------------------------- tensor-core GEMM (bf16x3) ----------------------

__device__ __forceinline__ void mma16816(float* c, const unsigned* a, const unsigned* b) {
    asm volatile(
        "mma.sync.aligned.m16n8k16.row.col.f32.bf16.bf16.f32 "
        "{%0,%1,%2,%3}, {%4,%5,%6,%7}, {%8,%9}, {%0,%1,%2,%3};\n"
        : "+f"(c[0]), "+f"(c[1]), "+f"(c[2]), "+f"(c[3])
        : "r"(a[0]), "r"(a[1]), "r"(a[2]), "r"(a[3]), "r"(b[0]), "r"(b[1]));
}
__device__ __forceinline__ void ldsm4(unsigned* r, uint32_t addr) {
    asm volatile("ldmatrix.sync.aligned.m8n8.x4.shared.b16 {%0,%1,%2,%3}, [%4];\n"
        : "=r"(r[0]), "=r"(r[1]), "=r"(r[2]), "=r"(r[3]) : "r"(addr));
}

// out[m][j] = sum_k mean[m][k]*W[j][k] + sum_k Ax[m][k]*W[j][128+k] + bias[j]
// FUSE: + ReLU + LayerNorm. A operands fp32 in gmem, split hi/lo at tile load.
// BM=128, BK=32, 256 threads (8 warps), warp tile m16 x nBN (whole rows).
// __launch_bounds__(256, 2): 2 CTAs/SM (smem 41KB static, regs capped 128)
// so cross-CTA overlap hides the sync-exposed tile-load latency.
template <int BN, bool FUSE>
__global__ __launch_bounds__(256, 2) void k_mma(
    const float* __restrict__ Ax,
    const __nv_bfloat16* __restrict__ Wh,      // [BN][256] concat [Wl|Wr] hi
    const __nv_bfloat16* __restrict__ Wl_,     // lo
    const float* __restrict__ bias,
    const float* __restrict__ gamma, const float* __restrict__ beta,
    float* __restrict__ out, int n)
{
    constexpr int BM = 128, BK = 32;
    constexpr int LDA = BK + 8;            // 40 bf16 row stride (80B, 16B-mult)
    constexpr int NT = BN / 8;             // n-tiles per warp row stripe

    __shared__ __align__(16) __nv_bfloat16 Ash[BM * LDA];
    __shared__ __align__(16) __nv_bfloat16 Asl[BM * LDA];
    __shared__ __align__(16) __nv_bfloat16 Bsh[BN * LDA];
    __shared__ __align__(16) __nv_bfloat16 Bsl[BN * LDA];

    const int tid = threadIdx.x;
    const int lane = tid & 31, warp = tid >> 5;
    const int rowBase = blockIdx.x * BM;

    float c[NT][4];
#pragma unroll
    for (int j = 0; j < NT; j++)
#pragma unroll
        for (int q = 0; q < 4; q++) c[j][q] = 0.f;

    const uint32_t ahBase = (uint32_t)__cvta_generic_to_shared(Ash);
    const uint32_t alBase = (uint32_t)__cvta_generic_to_shared(Asl);
    const uint32_t bhBase = (uint32_t)__cvta_generic_to_shared(Bsh);
    const uint32_t blBase = (uint32_t)__cvta_generic_to_shared(Bsl);
    const uint32_t aOff =
        (uint32_t)(((warp * 16 + (lane & 15)) * LDA + ((lane >> 4) << 3)) * 2);
    const int bRow = (lane & 7) + ((lane >> 4) << 3);   // n within 16-tile
    const int bKof = ((lane >> 3) & 1) << 3;            // k offset 0/8

    // 8 K-steps of 32: t=0..3 -> (g_mean, W[:,0:128]); t=4..7 -> (Ax, W[:,128:])
    for (int t = 0; t < 8; t++) {
        const float* A = (t < 4) ? g_mean : Ax;
        const int k0 = (t & 3) * BK;

        // A tile: BM x 32 fp32 -> split to bf16 hi/lo. 8 values per thread-chunk.
#pragma unroll
        for (int i = 0; i < (BM * 4) / 256; i++) {
            int q = tid + i * 256;
            int row = q >> 2, c8 = q & 3;
            float v[8];
            int gr = rowBase + row;
            if (gr < n) {
                float4 v0 = *(const float4*)(A + gr * 128 + k0 + c8 * 8);
                float4 v1 = *(const float4*)(A + gr * 128 + k0 + c8 * 8 + 4);
                v[0] = v0.x; v[1] = v0.y; v[2] = v0.z; v[3] = v0.w;
                v[4] = v1.x; v[5] = v1.y; v[6] = v1.z; v[7] = v1.w;
            } else {
#pragma unroll
                for (int j = 0; j < 8; j++) v[j] = 0.f;
            }
            __nv_bfloat16 h[8], l[8];
#pragma unroll
            for (int j = 0; j < 8; j++) {
                h[j] = __float2bfloat16(v[j]);
                l[j] = __float2bfloat16(v[j] - __bfloat162float(h[j]));
            }
            *(uint4*)(&Ash[row * LDA + c8 * 8]) = *(uint4*)h;
            *(uint4*)(&Asl[row * LDA + c8 * 8]) = *(uint4*)l;
        }
        // B tile: BN x 32 from pre-split weights
#pragma unroll
        for (int i = 0; i < (BN * 4) / 256; i++) {
            int q = tid + i * 256;
            int row = q >> 2, c8 = q & 3;
            *(uint4*)(&Bsh[row * LDA + c8 * 8]) =
                *(const uint4*)(Wh + row * 256 + t * 32 + c8 * 8);
            *(uint4*)(&Bsl[row * LDA + c8 * 8]) =
                *(const uint4*)(Wl_ + row * 256 + t * 32 + c8 * 8);
        }
        __syncthreads();

#pragma unroll
        for (int kk = 0; kk < BK; kk += 16) {
            unsigned ah[4], al[4];
            ldsm4(ah, ahBase + aOff + (uint32_t)(kk * 2));
            ldsm4(al, alBase + aOff + (uint32_t)(kk * 2));
#pragma unroll
            for (int jp = 0; jp < NT / 2; jp++) {
                unsigned bh[4], bl[4];
                uint32_t bo = (uint32_t)(((jp * 16 + bRow) * LDA + kk + bKof) * 2);
                ldsm4(bh, bhBase + bo);
                ldsm4(bl, blBase + bo);
                mma16816(c[2 * jp], ah, bh);
                mma16816(c[2 * jp], ah, bl);
                mma16816(c[2 * jp], al, bh);
                mma16816(c[2 * jp + 1], ah, bh + 2);
                mma16816(c[2 * jp + 1], ah, bl + 2);
                mma16816(c[2 * jp + 1], al, bh + 2);
            }
        }
        __syncthreads();
    }

    // ---- epilogue ----
    const int r0 = rowBase + warp * 16 + (lane >> 2);
    const int r1 = r0 + 8;
    const int cb = (lane & 3) * 2;

    if constexpr (FUSE) {
        float s0 = 0.f, ss0 = 0.f, s1 = 0.f, ss1 = 0.f;
#pragma unroll
        for (int j = 0; j < NT; j++) {
            float b0 = bias[j * 8 + cb], b1 = bias[j * 8 + cb + 1];
            c[j][0] = fmaxf(c[j][0] + b0, 0.f);
            c[j][1] = fmaxf(c[j][1] + b1, 0.f);
            c[j][2] = fmaxf(c[j][2] + b0, 0.f);
            c[j][3] = fmaxf(c[j][3] + b1, 0.f);
            s0 += c[j][0] + c[j][1]; ss0 += c[j][0] * c[j][0] + c[j][1] * c[j][1];
            s1 += c[j][2] + c[j][3]; ss1 += c[j][2] * c[j][2] + c[j][3] * c[j][3];
        }
#pragma unroll
        for (int o = 1; o <= 2; o <<= 1) {
            s0 += __shfl_xor_sync(0xffffffffu, s0, o);
            ss0 += __shfl_xor_sync(0xffffffffu, ss0, o);
            s1 += __shfl_xor_sync(0xffffffffu, s1, o);
            ss1 += __shfl_xor_sync(0xffffffffu, ss1, o);
        }
        const float inv = 1.0f / 128.0f;
        float mu0 = s0 * inv, var0 = ss0 * inv - mu0 * mu0;
        float mu1 = s1 * inv, var1 = ss1 * inv - mu1 * mu1;
        float rs0 = rsqrtf(var0 + 1e-5f);
        float rs1 = rsqrtf(var1 + 1e-5f);
#pragma unroll
        for (int j = 0; j < NT; j++) {
            float g0 = gamma[j * 8 + cb], g1v = gamma[j * 8 + cb + 1];
            float e0 = beta[j * 8 + cb],  e1 = beta[j * 8 + cb + 1];
            if (r0 < n)
                *(float2*)(out + r0 * 128 + j * 8 + cb) = make_float2(
                    (c[j][0] - mu0) * rs0 * g0 + e0,
                    (c[j][1] - mu0) * rs0 * g1v + e1);
            if (r1 < n)
                *(float2*)(out + r1 * 128 + j * 8 + cb) = make_float2(
                    (c[j][2] - mu1) * rs1 * g0 + e0,
                    (c[j][3] - mu1) * rs1 * g1v + e1);
        }
    } else {
#pragma unroll
        for (int j = 0; j < NT; j++) {
            float b0 = bias[j * 8 + cb], b1 = bias[j * 8 + cb + 1];
            if (r0 < n)
                *(float2*)(out + r0 * BN + j * 8 + cb) =
                    make_float2(c[j][0] + b0, c[j][1] + b1);
            if (r1 < n)
                *(float2*)(out + r1 * BN + j * 8 + cb) =
                    make_float2(c[j][2] + b0, c[j][3] + b1);
        }
    }
}

// --------------------------- launch ----------------------------------------

extern "C" void kernel_launch(void* const* d_in, const int* in_sizes, int n_in,
                              void* d_out, int out_size)
{
    const float* x   = (const float*)d_in[0];
    const void*  ei  = d_in[1];
    const float* Wl1 = (const float*)d_in[2];
    const float* bl1 = (const float*)d_in[3];
    const float* Wr1 = (const float*)d_in[4];
    const float* Wl2 = (const float*)d_in[5];
    const float* bl2 = (const float*)d_in[6];
    const float* Wr2 = (const float*)d_in[7];
    const float* Wl3 = (const float*)d_in[8];
    const float* bl3 = (const float*)d_in[9];
    const float* Wr3 = (const float*)d_in[10];
    const float* g1  = (const float*)d_in[11];
    const float* be1 = (const float*)d_in[12];
    const float* g2  = (const float*)d_in[13];
    const float* be2 = (const float*)d_in[14];

    const int n = in_sizes[0] / C;       // 50000
    const int E = in_sizes[1] / 2;       // 800000

    const int TB = 256;
    const int nb = (n + 1023) / 1024;    // 49 scan blocks

    // ---- CSR build (parallel scan) + weight split ----
    k_detect<<<1, TB>>>((const unsigned*)ei);
    k_zero<<<(n + TB - 1) / TB, TB>>>(n);
    k_convert<<<(E + TB - 1) / TB, TB>>>(ei, E);      // + hist
    k_scan1<<<nb, 1024>>>(n);
    k_scan2<<<1, 64>>>(nb);
    k_scan3<<<(n + TB - 1) / TB, TB>>>(n, E);          // + invc
    k_scatter<<<(E + TB - 1) / TB, TB>>>(E);

    __nv_bfloat16 *w1h, *w1l, *w2h, *w2l, *w3h, *w3l;
    cudaGetSymbolAddress((void**)&w1h, g_w1h);
    cudaGetSymbolAddress((void**)&w1l, g_w1l);
    cudaGetSymbolAddress((void**)&w2h, g_w2h);
    cudaGetSymbolAddress((void**)&w2l, g_w2l);
    cudaGetSymbolAddress((void**)&w3h, g_w3h);
    cudaGetSymbolAddress((void**)&w3l, g_w3l);
    k_cvt_w<<<(128 * 256 + TB - 1) / TB, TB>>>(Wl1, Wr1, w1h, w1l, 128);
    k_cvt_w<<<(128 * 256 + TB - 1) / TB, TB>>>(Wl2, Wr2, w2h, w2l, 128);
    k_cvt_w<<<(64 * 256 + TB - 1) / TB, TB>>>(Wl3, Wr3, w3h, w3l, 64);

    float *h1p, *h2p;
    cudaGetSymbolAddress((void**)&h1p, g_h1);
    cudaGetSymbolAddress((void**)&h2p, g_h2);

    const int aggGrid  = (n + 7) / 8;       // 8 warps/block, warp per node
    const int gemmGrid = (n + 127) / 128;

    // ---- layer 1 ----
    k_agg<<<aggGrid, TB>>>(x, 0, n);
    k_mma<128, true><<<gemmGrid, TB>>>(x, w1h, w1l, bl1, g1, be1, h1p, n);
    // ---- layer 2 ----
    k_agg<<<aggGrid, TB>>>(x, 1, n);
    k_mma<128, true><<<gemmGrid, TB>>>(h1p, w2h, w2l, bl2, g2, be2, h2p, n);
    // ---- layer 3 (64 outputs, no ReLU/LN) ----
    k_agg<<<aggGrid, TB>>>(x, 2, n);
    k_mma<64, false><<<gemmGrid, TB>>>(h2p, w3h, w3l, bl3, nullptr, nullptr,
                                       (float*)d_out, n);
}

// round 17
// speedup vs baseline: 1.0282x; 1.0171x over previous
#include <cstdint>
#include <cuda_runtime.h>
#include <cuda_bf16.h>
#include <cuda_fp16.h>

// ---------------------------------------------------------------------------
// GnnEncoder: 3-layer GraphSAGE (mean aggr) + ReLU + LayerNorm.
// R16 = R11 (best, 234.2us) with ONE change: GEMM emulation switched from
// bf16x3 (3 fp32-accum MMAs) to fp16x3 with DUAL-PRECISION accumulation:
//   main   Ah*Bh -> mma f32-accum (full rate precision)
//   corr   Ah*Bl + Al*Bh -> mma f16-accum (2x issue rate on HMMA)
// fp16 hi/lo = 21 effective mantissa bits; dropped lo*lo ~ 2.4e-7 relative.
// Per warp-tile: 2 f32-acc + 4 f16-acc MMAs vs 6 f32-acc -> ~33% mma cost.
// ---------------------------------------------------------------------------

static constexpr int NN = 50000;
static constexpr int EE = 800000;
static constexpr int C  = 128;

// scratch (static __device__ allocations: allowed)
__device__ float g_mean[NN * C];
__device__ float g_h1[NN * C];
__device__ float g_h2[NN * C];
__device__ __half g_w1h[128 * 256];
__device__ __half g_w1l[128 * 256];
__device__ __half g_w2h[128 * 256];
__device__ __half g_w2l[128 * 256];
__device__ __half g_w3h[64 * 256];
__device__ __half g_w3l[64 * 256];
__device__ int   g_src[EE];
__device__ int   g_dst[EE];
__device__ int   g_csr[EE];
__device__ int   g_off[NN + 1];
__device__ int   g_cnt[NN];
__device__ int   g_cur[NN];
__device__ int   g_bsum[64];
__device__ int   g_bsumx[64];
__device__ float g_invc[NN];
__device__ int   g_is64;

// --------------------------- index prep ------------------------------------

__global__ void k_detect(const unsigned* __restrict__ buf) {
    int nz = 0;
    for (int i = threadIdx.x; i < 512; i += blockDim.x)
        if (buf[2 * i + 1] != 0u) nz = 1;
    nz = __syncthreads_or(nz);
    if (threadIdx.x == 0) g_is64 = (nz == 0) ? 1 : 0;
}

__global__ void k_zero(int n) {
    int i = blockIdx.x * blockDim.x + threadIdx.x;
    if (i < n) { g_cnt[i] = 0; g_cur[i] = 0; }
}

// convert edge indices to int32 AND histogram dst (fused)
__global__ void k_convert(const void* __restrict__ buf, int E) {
    int e = blockIdx.x * blockDim.x + threadIdx.x;
    if (e >= E) return;
    int s, d;
    if (g_is64) {
        const long long* p = (const long long*)buf;
        s = (int)p[e]; d = (int)p[E + e];
    } else {
        const int* p = (const int*)buf;
        s = p[e]; d = p[E + e];
    }
    g_src[e] = s; g_dst[e] = d;
    atomicAdd(&g_cnt[d], 1);
}

// ---- hierarchical scan ----
__global__ __launch_bounds__(1024) void k_scan1(int n) {
    __shared__ int sh[1024];
    const int tid = threadIdx.x;
    int i = blockIdx.x * 1024 + tid;
    int v = (i < n) ? g_cnt[i] : 0;
    sh[tid] = v;
    __syncthreads();
    for (int off = 1; off < 1024; off <<= 1) {
        int t = (tid >= off) ? sh[tid - off] : 0;
        __syncthreads();
        sh[tid] += t;
        __syncthreads();
    }
    if (i < n) g_off[i] = sh[tid] - v;        // exclusive within block
    if (tid == 1023) g_bsum[blockIdx.x] = sh[1023];
}

__global__ void k_scan2(int nb) {
    __shared__ int sh[64];
    const int tid = threadIdx.x;
    int v = (tid < nb) ? g_bsum[tid] : 0;
    sh[tid] = v;
    __syncthreads();
    for (int off = 1; off < 64; off <<= 1) {
        int t = (tid >= off) ? sh[tid - off] : 0;
        __syncthreads();
        sh[tid] += t;
        __syncthreads();
    }
    if (tid < nb) g_bsumx[tid] = sh[tid] - v; // exclusive
}

__global__ void k_scan3(int n, int E) {
    int i = blockIdx.x * blockDim.x + threadIdx.x;
    if (i < n) {
        g_off[i] += g_bsumx[i >> 10];
        int cnt = g_cnt[i];
        g_invc[i] = 1.0f / (float)(cnt > 0 ? cnt : 1);
    }
    if (i == 0) g_off[n] = E;
}

__global__ void k_scatter(int E) {
    int e = blockIdx.x * blockDim.x + threadIdx.x;
    if (e >= E) return;
    int d = g_dst[e];
    int p = atomicAdd(&g_cur[d], 1);
    g_csr[g_off[d] + p] = g_src[e];
}

// --------------------------- weight split (fp16 hi/lo) ----------------------
__global__ void k_cvt_w(const float* __restrict__ Wl, const float* __restrict__ Wr,
                        __half* __restrict__ dh, __half* __restrict__ dl,
                        int N) {
    int i = blockIdx.x * blockDim.x + threadIdx.x;
    if (i >= N * 256) return;
    int nrow = i >> 8, k = i & 255;
    float v = (k < 128) ? Wl[nrow * 128 + k] : Wr[nrow * 128 + (k - 128)];
    __half h = __float2half_rn(v);
    dh[i] = h;
    dl[i] = __float2half_rn(v - __half2float(h));
}

// --------------------------- aggregation (fp32) -----------------------------
__global__ __launch_bounds__(256) void k_agg(const float* __restrict__ xext,
                                             int insel, int n) {
    const float* xin = (insel == 0) ? xext : (insel == 1) ? g_h1 : g_h2;
    int warp = (blockIdx.x * blockDim.x + threadIdx.x) >> 5;
    int lane = threadIdx.x & 31;
    if (warp >= n) return;
    int s0 = g_off[warp], s1 = g_off[warp + 1];
    const float4* xin4 = (const float4*)xin;
    float4 acc = make_float4(0.f, 0.f, 0.f, 0.f);
    int i = s0;
    for (; i + 1 < s1; i += 2) {
        int a = g_csr[i], b = g_csr[i + 1];
        float4 va = xin4[a * 32 + lane];
        float4 vb = xin4[b * 32 + lane];
        acc.x += va.x + vb.x; acc.y += va.y + vb.y;
        acc.z += va.z + vb.z; acc.w += va.w + vb.w;
    }
    if (i < s1) {
        int a = g_csr[i];
        float4 va = xin4[a * 32 + lane];
        acc.x += va.x; acc.y += va.y; acc.z += va.z; acc.w += va.w;
    }
    float ic = g_invc[warp];
    acc.x *= ic; acc.y *= ic; acc.z *= ic; acc.w *= ic;
    ((float4*)g_mean)[warp * 32 + lane] = acc;
}

// --------------------------- tensor-core GEMM (fp16x3, dual accum) ----------

__device__ __forceinline__ void mma_f32(float* c, const unsigned* a, const unsigned* b) {
    asm volatile(
        "mma.sync.aligned.m16n8k16.row.col.f32.f16.f16.f32 "
        "{%0,%1,%2,%3}, {%4,%5,%6,%7}, {%8,%9}, {%0,%1,%2,%3};\n"
        : "+f"(c[0]), "+f"(c[1]), "+f"(c[2]), "+f"(c[3])
        : "r"(a[0]), "r"(a[1]), "r"(a[2]), "r"(a[3]), "r"(b[0]), "r"(b[1]));
}
__device__ __forceinline__ void mma_f16(unsigned* d, const unsigned* a, const unsigned* b) {
    asm volatile(
        "mma.sync.aligned.m16n8k16.row.col.f16.f16.f16.f16 "
        "{%0,%1}, {%2,%3,%4,%5}, {%6,%7}, {%0,%1};\n"
        : "+r"(d[0]), "+r"(d[1])
        : "r"(a[0]), "r"(a[1]), "r"(a[2]), "r"(a[3]), "r"(b[0]), "r"(b[1]));
}
__device__ __forceinline__ void ldsm4(unsigned* r, uint32_t addr) {
    asm volatile("ldmatrix.sync.aligned.m8n8.x4.shared.b16 {%0,%1,%2,%3}, [%4];\n"
        : "=r"(r[0]), "=r"(r[1]), "=r"(r[2]), "=r"(r[3]) : "r"(addr));
}

// out[m][j] = sum_k mean[m][k]*W[j][k] + sum_k Ax[m][k]*W[j][128+k] + bias[j]
// FUSE: + ReLU + LayerNorm. A operands fp32 in gmem, split fp16 hi/lo at STS.
// BM=128, BK=32, 256 threads (8 warps), warp tile m16 x nBN (whole rows).
// Pipeline: LDG tile t+2 -> regs, STS tile t+1 -> alt smem stage, compute t.
template <int BN, bool FUSE>
__global__ __launch_bounds__(256) void k_mma(
    const float* __restrict__ Ax,
    const __half* __restrict__ Wh,      // [BN][256] concat [Wl|Wr] hi
    const __half* __restrict__ Wl_,     // lo
    const float* __restrict__ bias,
    const float* __restrict__ gamma, const float* __restrict__ beta,
    float* __restrict__ out, int n)
{
    constexpr int BM = 128, BK = 32;
    constexpr int LDA = BK + 8;            // 40 f16 row stride (80B, 16B-mult)
    constexpr int NT = BN / 8;             // n-tiles per warp row stripe
    constexpr int NB = (BN * 4) / 256;     // B chunks per thread (2 or 1)
    constexpr int AH = 0;
    constexpr int AL = BM * LDA;
    constexpr int BH = 2 * BM * LDA;
    constexpr int BL = 2 * BM * LDA + BN * LDA;
    constexpr int STAGE = 2 * BM * LDA + 2 * BN * LDA;   // elements
    constexpr int STAGE_B = STAGE * 2;                    // bytes

    extern __shared__ __align__(16) __half smem[];

    const int tid = threadIdx.x;
    const int lane = tid & 31, warp = tid >> 5;
    const int rowBase = blockIdx.x * BM;
    const uint32_t sBase = (uint32_t)__cvta_generic_to_shared(smem);

    float c[NT][4];
    unsigned ch[NT][2];                 // f16x2 correction accumulators
#pragma unroll
    for (int j = 0; j < NT; j++) {
#pragma unroll
        for (int q = 0; q < 4; q++) c[j][q] = 0.f;
        ch[j][0] = 0u; ch[j][1] = 0u;
    }

    float va[2][8];
    uint4 vbh[2], vbl[2];

    auto ldg_tile = [&](int t) {
        const float* A = (t < 4) ? g_mean : Ax;
        const int k0 = (t & 3) * BK;
#pragma unroll
        for (int i = 0; i < 2; i++) {
            int q = tid + i * 256;
            int row = q >> 2, c8 = q & 3;
            int gr = rowBase + row;
            if (gr < n) {
                float4 v0 = *(const float4*)(A + gr * 128 + k0 + c8 * 8);
                float4 v1 = *(const float4*)(A + gr * 128 + k0 + c8 * 8 + 4);
                va[i][0] = v0.x; va[i][1] = v0.y; va[i][2] = v0.z; va[i][3] = v0.w;
                va[i][4] = v1.x; va[i][5] = v1.y; va[i][6] = v1.z; va[i][7] = v1.w;
            } else {
#pragma unroll
                for (int j = 0; j < 8; j++) va[i][j] = 0.f;
            }
        }
#pragma unroll
        for (int i = 0; i < NB; i++) {
            int q = tid + i * 256;
            int row = q >> 2, c8 = q & 3;
            vbh[i] = *(const uint4*)(Wh  + row * 256 + t * BK + c8 * 8);
            vbl[i] = *(const uint4*)(Wl_ + row * 256 + t * BK + c8 * 8);
        }
    };
    auto sts_tile = [&](int s) {
        __half* st = smem + s * STAGE;
#pragma unroll
        for (int i = 0; i < 2; i++) {
            int q = tid + i * 256;
            int row = q >> 2, c8 = q & 3;
            __half h[8], l[8];
#pragma unroll
            for (int j = 0; j < 8; j++) {
                h[j] = __float2half_rn(va[i][j]);
                l[j] = __float2half_rn(va[i][j] - __half2float(h[j]));
            }
            *(uint4*)(st + AH + row * LDA + c8 * 8) = *(uint4*)h;
            *(uint4*)(st + AL + row * LDA + c8 * 8) = *(uint4*)l;
        }
#pragma unroll
        for (int i = 0; i < NB; i++) {
            int q = tid + i * 256;
            int row = q >> 2, c8 = q & 3;
            *(uint4*)(st + BH + row * LDA + c8 * 8) = vbh[i];
            *(uint4*)(st + BL + row * LDA + c8 * 8) = vbl[i];
        }
    };

    const uint32_t aOff =
        (uint32_t)(((warp * 16 + (lane & 15)) * LDA + ((lane >> 4) << 3)) * 2);
    const int bRow = (lane & 7) + ((lane >> 4) << 3);   // n within 16-tile
    const int bKof = ((lane >> 3) & 1) << 3;            // k offset 0/8

    ldg_tile(0);
    sts_tile(0);
    ldg_tile(1);

    // 8 K-steps of 32: t=0..3 -> (g_mean, W[:,0:128]); t=4..7 -> (Ax, W[:,128:])
    for (int t = 0; t < 8; t++) {
        __syncthreads();
        if (t + 1 < 8) sts_tile((t + 1) & 1);
        if (t + 2 < 8) ldg_tile(t + 2);

        const uint32_t st = sBase + (t & 1) * STAGE_B;
#pragma unroll
        for (int kk = 0; kk < BK; kk += 16) {
            unsigned ah[4], al[4];
            ldsm4(ah, st + AH * 2 + aOff + (uint32_t)(kk * 2));
            ldsm4(al, st + AL * 2 + aOff + (uint32_t)(kk * 2));
#pragma unroll
            for (int jp = 0; jp < NT / 2; jp++) {
                unsigned bh[4], bl[4];
                uint32_t bo = (uint32_t)(((jp * 16 + bRow) * LDA + kk + bKof) * 2);
                ldsm4(bh, st + BH * 2 + bo);
                ldsm4(bl, st + BL * 2 + bo);
                // main terms: f32 accumulation
                mma_f32(c[2 * jp],     ah, bh);
                mma_f32(c[2 * jp + 1], ah, bh + 2);
                // correction terms: f16 accumulation (2x rate)
                mma_f16(ch[2 * jp],     ah, bl);
                mma_f16(ch[2 * jp],     al, bh);
                mma_f16(ch[2 * jp + 1], ah, bl + 2);
                mma_f16(ch[2 * jp + 1], al, bh + 2);
            }
        }
    }

    // fold f16 corrections into fp32 accumulators
#pragma unroll
    for (int j = 0; j < NT; j++) {
        float2 p0 = __half22float2(*(__half2*)&ch[j][0]);
        float2 p1 = __half22float2(*(__half2*)&ch[j][1]);
        c[j][0] += p0.x; c[j][1] += p0.y;
        c[j][2] += p1.x; c[j][3] += p1.y;
    }

    // ---- epilogue ----
    const int r0 = rowBase + warp * 16 + (lane >> 2);
    const int r1 = r0 + 8;
    const int cb = (lane & 3) * 2;

    if constexpr (FUSE) {
        float s0 = 0.f, ss0 = 0.f, s1 = 0.f, ss1 = 0.f;
#pragma unroll
        for (int j = 0; j < NT; j++) {
            float b0 = bias[j * 8 + cb], b1 = bias[j * 8 + cb + 1];
            c[j][0] = fmaxf(c[j][0] + b0, 0.f);
            c[j][1] = fmaxf(c[j][1] + b1, 0.f);
            c[j][2] = fmaxf(c[j][2] + b0, 0.f);
            c[j][3] = fmaxf(c[j][3] + b1, 0.f);
            s0 += c[j][0] + c[j][1]; ss0 += c[j][0] * c[j][0] + c[j][1] * c[j][1];
            s1 += c[j][2] + c[j][3]; ss1 += c[j][2] * c[j][2] + c[j][3] * c[j][3];
        }
#pragma unroll
        for (int o = 1; o <= 2; o <<= 1) {
            s0 += __shfl_xor_sync(0xffffffffu, s0, o);
            ss0 += __shfl_xor_sync(0xffffffffu, ss0, o);
            s1 += __shfl_xor_sync(0xffffffffu, s1, o);
            ss1 += __shfl_xor_sync(0xffffffffu, ss1, o);
        }
        const float inv = 1.0f / 128.0f;
        float mu0 = s0 * inv, var0 = ss0 * inv - mu0 * mu0;
        float mu1 = s1 * inv, var1 = ss1 * inv - mu1 * mu1;
        float rs0 = rsqrtf(var0 + 1e-5f);
        float rs1 = rsqrtf(var1 + 1e-5f);
#pragma unroll
        for (int j = 0; j < NT; j++) {
            float g0 = gamma[j * 8 + cb], g1v = gamma[j * 8 + cb + 1];
            float e0 = beta[j * 8 + cb],  e1 = beta[j * 8 + cb + 1];
            if (r0 < n)
                *(float2*)(out + r0 * 128 + j * 8 + cb) = make_float2(
                    (c[j][0] - mu0) * rs0 * g0 + e0,
                    (c[j][1] - mu0) * rs0 * g1v + e1);
            if (r1 < n)
                *(float2*)(out + r1 * 128 + j * 8 + cb) = make_float2(
                    (c[j][2] - mu1) * rs1 * g0 + e0,
                    (c[j][3] - mu1) * rs1 * g1v + e1);
        }
    } else {
#pragma unroll
        for (int j = 0; j < NT; j++) {
            float b0 = bias[j * 8 + cb], b1 = bias[j * 8 + cb + 1];
            if (r0 < n)
                *(float2*)(out + r0 * BN + j * 8 + cb) =
                    make_float2(c[j][0] + b0, c[j][1] + b1);
            if (r1 < n)
                *(float2*)(out + r1 * BN + j * 8 + cb) =
                    make_float2(c[j][2] + b0, c[j][3] + b1);
        }
    }
}

// --------------------------- launch ----------------------------------------

extern "C" void kernel_launch(void* const* d_in, const int* in_sizes, int n_in,
                              void* d_out, int out_size)
{
    const float* x   = (const float*)d_in[0];
    const void*  ei  = d_in[1];
    const float* Wl1 = (const float*)d_in[2];
    const float* bl1 = (const float*)d_in[3];
    const float* Wr1 = (const float*)d_in[4];
    const float* Wl2 = (const float*)d_in[5];
    const float* bl2 = (const float*)d_in[6];
    const float* Wr2 = (const float*)d_in[7];
    const float* Wl3 = (const float*)d_in[8];
    const float* bl3 = (const float*)d_in[9];
    const float* Wr3 = (const float*)d_in[10];
    const float* g1  = (const float*)d_in[11];
    const float* be1 = (const float*)d_in[12];
    const float* g2  = (const float*)d_in[13];
    const float* be2 = (const float*)d_in[14];

    const int n = in_sizes[0] / C;       // 50000
    const int E = in_sizes[1] / 2;       // 800000

    const int TB = 256;
    const int nb = (n + 1023) / 1024;    // 49 scan blocks

    // dynamic smem (2 stages): BN=128 -> 81920B, BN=64 -> 61440B
    constexpr int LDA = 40;
    const int smem128 = 2 * (2 * 128 * LDA + 2 * 128 * LDA) * 2;
    const int smem64  = 2 * (2 * 128 * LDA + 2 * 64  * LDA) * 2;
    static bool attr_done = false;
    if (!attr_done) {
        cudaFuncSetAttribute(k_mma<128, true>,
            cudaFuncAttributeMaxDynamicSharedMemorySize, smem128);
        cudaFuncSetAttribute(k_mma<64, false>,
            cudaFuncAttributeMaxDynamicSharedMemorySize, smem64);
        attr_done = true;
    }

    // ---- CSR build (parallel scan) + weight split ----
    k_detect<<<1, TB>>>((const unsigned*)ei);
    k_zero<<<(n + TB - 1) / TB, TB>>>(n);
    k_convert<<<(E + TB - 1) / TB, TB>>>(ei, E);      // + hist
    k_scan1<<<nb, 1024>>>(n);
    k_scan2<<<1, 64>>>(nb);
    k_scan3<<<(n + TB - 1) / TB, TB>>>(n, E);          // + invc
    k_scatter<<<(E + TB - 1) / TB, TB>>>(E);

    __half *w1h, *w1l, *w2h, *w2l, *w3h, *w3l;
    cudaGetSymbolAddress((void**)&w1h, g_w1h);
    cudaGetSymbolAddress((void**)&w1l, g_w1l);
    cudaGetSymbolAddress((void**)&w2h, g_w2h);
    cudaGetSymbolAddress((void**)&w2l, g_w2l);
    cudaGetSymbolAddress((void**)&w3h, g_w3h);
    cudaGetSymbolAddress((void**)&w3l, g_w3l);
    k_cvt_w<<<(128 * 256 + TB - 1) / TB, TB>>>(Wl1, Wr1, w1h, w1l, 128);
    k_cvt_w<<<(128 * 256 + TB - 1) / TB, TB>>>(Wl2, Wr2, w2h, w2l, 128);
    k_cvt_w<<<(64 * 256 + TB - 1) / TB, TB>>>(Wl3, Wr3, w3h, w3l, 64);

    float *h1p, *h2p;
    cudaGetSymbolAddress((void**)&h1p, g_h1);
    cudaGetSymbolAddress((void**)&h2p, g_h2);

    const int aggGrid  = (n + 7) / 8;       // 8 warps/block, warp per node
    const int gemmGrid = (n + 127) / 128;

    // ---- layer 1 ----
    k_agg<<<aggGrid, TB>>>(x, 0, n);
    k_mma<128, true><<<gemmGrid, TB, smem128>>>(x, w1h, w1l, bl1, g1, be1, h1p, n);
    // ---- layer 2 ----
    k_agg<<<aggGrid, TB>>>(x, 1, n);
    k_mma<128, true><<<gemmGrid, TB, smem128>>>(h1p, w2h, w2l, bl2, g2, be2, h2p, n);
    // ---- layer 3 (64 outputs, no ReLU/LN) ----
    k_agg<<<aggGrid, TB>>>(x, 2, n);
    k_mma<64, false><<<gemmGrid, TB, smem64>>>(h2p, w3h, w3l, bl3, nullptr, nullptr,
                                               (float*)d_out, n);
}